// round 15
// baseline (speedup 1.0000x reference)
#include <cuda_runtime.h>
#include <cuda_bf16.h>
#include <cuda_fp16.h>
#include <math.h>

#define BB 32
#define CTX 128
#define NF 128
#define NS 32768
#define NE 16
#define CH 256
#define WIN 512
#define NC 257
#define TC 514
#define TCL 576              // padded ld for xout/spec (re at 0, im at 288)
#define IMOFF 288
#define KPQ 288              // K for P/Q GEMM (257 padded; 9 K-tiles of 32)
#define NPQ 320              // padded t-range per half (10 x 32 N-blocks)
#define NPQ2 640
#define NROWS (BB*NF)        // 4096
#define NWO 576              // padded w_out rows

typedef __nv_bfloat16 bf;
typedef __half hf;

// ---------------- static scratch (zero-initialized at load; pads stay 0) ----------------
__device__ float g_xout[NROWS*TCL];
__device__ float g_pq[NROWS*NPQ2];                 // P cols [0,320), Q cols [320,640)
__device__ float g_sig[BB*NS];
__device__ int   g_evcnt[BB*NE];
__device__ int   g_evf[BB*NE*NF];
__device__ float g_eva[BB*NE*NF];
__device__ float g_bout[NWO];
// bf16 hi/lo operands (MLP path, 3-term split)
__device__ bf g_a0h[NROWS*CH], g_a0l[NROWS*CH];
__device__ bf g_a1h[NROWS*CH], g_a1l[NROWS*CH];
__device__ bf g_w0h[CH*CH],  g_w0l[CH*CH];
__device__ bf g_w1h[CH*CH],  g_w1l[CH*CH];
__device__ bf g_w2h[CH*CH],  g_w2l[CH*CH];
__device__ bf g_woh[NWO*CH], g_wol[NWO*CH];
// fp16 operands (irfft path): basis rows [0,320)=cos, [320,640)=sin; spec hi/lo
__device__ hf g_basPQ[NPQ2*KPQ];
__device__ hf g_sphH[NROWS*TCL], g_splH[NROWS*TCL];

// ---------------- helpers ----------------
__device__ __forceinline__ void split1(float v, bf& h, bf& l) {
    h = __float2bfloat16(v);
    l = __float2bfloat16(v - __bfloat162float(h));
}
__device__ __forceinline__ void split1h(float v, hf& h, hf& l) {
    h = __float2half(v);
    l = __float2half(v - __half2float(h));
}
__device__ __forceinline__ void cp16(void* dst, const void* src) {
    unsigned d = (unsigned)__cvta_generic_to_shared(dst);
    asm volatile("cp.async.ca.shared.global [%0], [%1], 16;" :: "r"(d), "l"(src));
}
#define CP_COMMIT() asm volatile("cp.async.commit_group;")
#define CP_WAIT1()  asm volatile("cp.async.wait_group 1;")
#define CP_WAIT0()  asm volatile("cp.async.wait_group 0;")

__device__ __forceinline__ void ldsm4(unsigned& r0, unsigned& r1, unsigned& r2, unsigned& r3,
                                      const void* p) {
    unsigned a = (unsigned)__cvta_generic_to_shared(p);
    asm volatile("ldmatrix.sync.aligned.m8n8.x4.shared.b16 {%0,%1,%2,%3}, [%4];"
                 : "=r"(r0), "=r"(r1), "=r"(r2), "=r"(r3) : "r"(a));
}

#define MMA_BF16(d, a, b) \
    asm volatile("mma.sync.aligned.m16n8k16.row.col.f32.bf16.bf16.f32 " \
                 "{%0,%1,%2,%3},{%4,%5,%6,%7},{%8,%9},{%0,%1,%2,%3};" \
                 : "+f"(d[0]), "+f"(d[1]), "+f"(d[2]), "+f"(d[3]) \
                 : "r"(a[0]), "r"(a[1]), "r"(a[2]), "r"(a[3]), "r"(b[0]), "r"(b[1]))

#define MMA_F16(d, a, b) \
    asm volatile("mma.sync.aligned.m16n8k16.row.col.f32.f16.f16.f32 " \
                 "{%0,%1,%2,%3},{%4,%5,%6,%7},{%8,%9},{%0,%1,%2,%3};" \
                 : "+f"(d[0]), "+f"(d[1]), "+f"(d[2]), "+f"(d[3]) \
                 : "r"(a[0]), "r"(a[1]), "r"(a[2]), "r"(a[3]), "r"(b[0]), "r"(b[1]))

// ---------------- prep: P/Q basis (fp16) + all weight converts + padded bias ----------------
#define NB_BAS (NPQ2*KPQ)
#define NV_W   (CH*CH/4)
#define NV_WO  (TC*CH/4)
#define PREP_TOTAL (NB_BAS + 3*NV_W + NV_WO + TC)
__global__ void prep_k(const float* __restrict__ w0, const float* __restrict__ w1,
                       const float* __restrict__ w2, const float* __restrict__ wo,
                       const float* __restrict__ b_out) {
    int idx = blockIdx.x*blockDim.x + threadIdx.x;
    if (idx < NB_BAS) {
        int row = idx / KPQ;
        int k = idx - row*KPQ;
        bool is_sin = (row >= NPQ);
        int t = is_sin ? row - NPQ : row;
        float val = 0.f;
        if (k < NC) {
            int m = (k * t) & (WIN - 1);
            float theta = (float)m * (float)(M_PI/256.0);
            float w = (k == 0 || k == NC-1) ? 1.f : 2.f;
            float v = is_sin ? sinf(theta) : cosf(theta);
            val = v * w * (1.f/512.f);
        }
        g_basPQ[idx] = __float2half(val);
        return;
    }
    int r = idx - NB_BAS;
    const float* src; bf* hi; bf* lo;
    if      (r < NV_W)          { src = w0; hi = g_w0h; lo = g_w0l; }
    else if (r < 2*NV_W)        { src = w1; hi = g_w1h; lo = g_w1l; r -= NV_W; }
    else if (r < 3*NV_W)        { src = w2; hi = g_w2h; lo = g_w2l; r -= 2*NV_W; }
    else if (r < 3*NV_W+NV_WO)  { src = wo; hi = g_woh; lo = g_wol; r -= 3*NV_W; }
    else if (r < 3*NV_W+NV_WO+TC) { g_bout[r - 3*NV_W - NV_WO] = b_out[r - 3*NV_W - NV_WO]; return; }
    else return;
    int i = r*4;
    float4 v = *(const float4*)(src + i);
    bf h0,h1,h2,h3,l0,l1,l2,l3;
    split1(v.x,h0,l0); split1(v.y,h1,l1); split1(v.z,h2,l2); split1(v.w,h3,l3);
    __nv_bfloat162 hh0 = {h0,h1}, hh1 = {h2,h3}, ll0 = {l0,l1}, ll1 = {l2,l3};
    *(uint2*)(hi + i) = make_uint2(*(unsigned*)&hh0, *(unsigned*)&hh1);
    *(uint2*)(lo + i) = make_uint2(*(unsigned*)&ll0, *(unsigned*)&ll1);
}

// ---------------- fused proj + addpos + split ----------------
__global__ void proj_addpos_k(const float* __restrict__ param, const float* __restrict__ proj_w,
                              const float* __restrict__ proj_b, const float* __restrict__ pos) {
    int b = blockIdx.x;
    int c = threadIdx.x;                    // 256
    __shared__ float pr[CTX];
    __shared__ float bs[CH];
    if (c < CTX) pr[c] = param[b*CTX + c];
    __syncthreads();
    float acc = proj_b[c];
    const float* wr = proj_w + (size_t)c*CTX;
    #pragma unroll 8
    for (int k = 0; k < CTX; ++k) acc = fmaf(pr[k], wr[k], acc);
    bs[c] = acc;
    __syncthreads();
    int c4 = (c & 63) * 4;
    int f0 = c >> 6;
    float4 vb = *(const float4*)&bs[c4];
    #pragma unroll 4
    for (int i = 0; i < 32; ++i) {
        int f = f0 + i*4;
        float4 vp = *(const float4*)(pos + (size_t)f*CH + c4);
        float4 v = make_float4(vb.x+vp.x, vb.y+vp.y, vb.z+vp.z, vb.w+vp.w);
        bf h0,h1,h2,h3,l0,l1,l2,l3;
        split1(v.x,h0,l0); split1(v.y,h1,l1); split1(v.z,h2,l2); split1(v.w,h3,l3);
        __nv_bfloat162 hh0 = {h0,h1}, hh1 = {h2,h3}, ll0 = {l0,l1}, ll1 = {l2,l3};
        size_t o = (size_t)(b*NF + f)*CH + c4;
        *(uint2*)(g_a0h + o) = make_uint2(*(unsigned*)&hh0, *(unsigned*)&hh1);
        *(uint2*)(g_a0l + o) = make_uint2(*(unsigned*)&ll0, *(unsigned*)&ll1);
    }
}

// ---------------- bf16 3-term GEMM: BM=64, BN=32, BK=32; 256 thr; 8 warps 4(m)x2(n) 16x16 ----------------
#define SM_ATILE (64*40)
#define SM_BTILE (32*40)
#define ASTG (2*SM_ATILE)
#define BSTG (2*SM_BTILE)
#define SB_OFF (3*ASTG)
#define SMEM_BYTES ((3*ASTG + 3*BSTG)*2)      // 46080

template<bool RELU, bool BIAS, bool SPLITOUT>
__global__ void __launch_bounds__(256) gemm7_k(
    const bf* __restrict__ Ah, const bf* __restrict__ Al,
    const bf* __restrict__ Wh, const bf* __restrict__ Wl,
    const float* __restrict__ bias,
    float* __restrict__ Cf, bf* __restrict__ Ch, bf* __restrict__ Cl,
    int M, int N, int K, int lda, int ldw, int ldc)
{
    extern __shared__ __align__(16) bf sm[];
    bf* sA = sm;
    bf* sB = sm + SB_OFF;

    int tid = threadIdx.x;
    int row0 = blockIdx.y * 64;
    int col0 = blockIdx.x * 32;

    int lrow = tid >> 2;               // 0..63 (A); 0..31 for B (tid<128)
    int lch  = (tid & 3) * 8;

    int wid  = tid >> 5;
    int lane = tid & 31;
    int wm0 = (wid >> 1) * 16;
    int wn0 = (wid & 1) * 16;
    int t = lane & 3;

    int q  = lane >> 3;
    int r8 = lane & 7;
    int a_row = wm0 + ((q & 1) << 3) + r8;
    int a_col = (q >> 1) << 3;
    int b_row = ((q >> 1) << 3) + r8;
    int b_col = (q & 1) << 3;

    auto prefetch = [&](int kt, int st) {
        int gk = kt*32 + lch;
        bf* pa = sA + st*ASTG + lrow*40 + lch;
        cp16(pa,            Ah + (size_t)(row0+lrow)*lda + gk);
        cp16(pa + SM_ATILE, Al + (size_t)(row0+lrow)*lda + gk);
        if (tid < 128) {
            bf* pb = sB + st*BSTG + lrow*40 + lch;
            cp16(pb,            Wh + (size_t)(col0+lrow)*ldw + gk);
            cp16(pb + SM_BTILE, Wl + (size_t)(col0+lrow)*ldw + gk);
        }
    };

    float acc[2][4];
    #pragma unroll
    for (int nt = 0; nt < 2; ++nt)
        #pragma unroll
        for (int i = 0; i < 4; ++i) acc[nt][i] = 0.f;

    int ktiles = K >> 5;
    prefetch(0, 0); CP_COMMIT();
    prefetch(1, 1); CP_COMMIT();

    for (int kt = 0; kt < ktiles; ++kt) {
        int st = kt % 3;
        if (kt + 1 < ktiles) { CP_WAIT1(); } else { CP_WAIT0(); }
        __syncthreads();
        const bf* cA = sA + st*ASTG;
        const bf* cB = sB + st*BSTG;

        #pragma unroll
        for (int kk = 0; kk < 32; kk += 16) {
            unsigned ah[4], al[4], bh[2][2], bl[2][2];
            ldsm4(ah[0], ah[1], ah[2], ah[3], cA + a_row*40 + kk + a_col);
            ldsm4(al[0], al[1], al[2], al[3], cA + SM_ATILE + a_row*40 + kk + a_col);
            ldsm4(bh[0][0], bh[0][1], bh[1][0], bh[1][1], cB + (wn0 + b_row)*40 + kk + b_col);
            ldsm4(bl[0][0], bl[0][1], bl[1][0], bl[1][1], cB + SM_BTILE + (wn0 + b_row)*40 + kk + b_col);
            #pragma unroll
            for (int nt = 0; nt < 2; ++nt) {
                MMA_BF16(acc[nt], ah, bh[nt]);
                MMA_BF16(acc[nt], ah, bl[nt]);
                MMA_BF16(acc[nt], al, bh[nt]);
            }
        }
        if (kt + 2 < ktiles) { prefetch(kt + 2, (kt + 2) % 3); CP_COMMIT(); }
    }

    int g = lane >> 2;
    #pragma unroll
    for (int nt = 0; nt < 2; ++nt) {
        int c = col0 + wn0 + nt*8 + 2*t;
        float b0 = BIAS ? bias[c]   : 0.f;
        float b1 = BIAS ? bias[c+1] : 0.f;
        int r0 = row0 + wm0 + g;
        float v[4] = {acc[nt][0] + b0, acc[nt][1] + b1,
                      acc[nt][2] + b0, acc[nt][3] + b1};
        if (RELU) {
            #pragma unroll
            for (int qq = 0; qq < 4; ++qq) v[qq] = (v[qq] > 0.f) ? v[qq] : 0.2f*v[qq];
        }
        if (SPLITOUT) {
            bf h0,h1,h2,h3,l0,l1,l2,l3;
            split1(v[0],h0,l0); split1(v[1],h1,l1);
            split1(v[2],h2,l2); split1(v[3],h3,l3);
            __nv_bfloat162 hA = {h0,h1}, hB = {h2,h3}, lA = {l0,l1}, lB = {l2,l3};
            *(__nv_bfloat162*)(Ch + (size_t)r0*ldc + c)     = hA;
            *(__nv_bfloat162*)(Ch + (size_t)(r0+8)*ldc + c) = hB;
            *(__nv_bfloat162*)(Cl + (size_t)r0*ldc + c)     = lA;
            *(__nv_bfloat162*)(Cl + (size_t)(r0+8)*ldc + c) = lB;
        } else {
            *(float2*)(Cf + (size_t)r0*ldc + c)     = make_float2(v[0], v[1]);
            *(float2*)(Cf + (size_t)(r0+8)*ldc + c) = make_float2(v[2], v[3]);
        }
    }
}

// ---------------- fp16 2-term GEMM (P/Q irfft path): BM=64, BN=32 ----------------
#define HB_OFF (3*ASTG)
#define HBSTG SM_BTILE
#define SMEMH_BYTES ((3*ASTG + 3*HBSTG)*2)   // 38400

__global__ void __launch_bounds__(256) gemmh_k(
    const hf* __restrict__ Ah0, const hf* __restrict__ Al0,
    const hf* __restrict__ W,
    float* __restrict__ Cf,
    int K, int lda, int ldw, int ldc)
{
    extern __shared__ __align__(16) hf smh[];
    hf* sA = smh;
    hf* sB = smh + HB_OFF;

    int tid = threadIdx.x;
    int row0 = blockIdx.y * 64;
    int col0 = blockIdx.x * 32;
    const hf* Ah = (col0 >= NPQ) ? Ah0 + IMOFF : Ah0;
    const hf* Al = (col0 >= NPQ) ? Al0 + IMOFF : Al0;

    int lrow = tid >> 2;
    int lch  = (tid & 3) * 8;

    int wid  = tid >> 5;
    int lane = tid & 31;
    int wm0 = (wid >> 1) * 16;
    int wn0 = (wid & 1) * 16;
    int t = lane & 3;

    int q  = lane >> 3;
    int r8 = lane & 7;
    int a_row = wm0 + ((q & 1) << 3) + r8;
    int a_col = (q >> 1) << 3;
    int b_row = ((q >> 1) << 3) + r8;
    int b_col = (q & 1) << 3;

    auto prefetch = [&](int kt, int st) {
        int gk = kt*32 + lch;
        hf* pa = sA + st*ASTG + lrow*40 + lch;
        cp16(pa,            Ah + (size_t)(row0+lrow)*lda + gk);
        cp16(pa + SM_ATILE, Al + (size_t)(row0+lrow)*lda + gk);
        if (tid < 128) {
            hf* pb = sB + st*HBSTG + lrow*40 + lch;
            cp16(pb, W + (size_t)(col0+lrow)*ldw + gk);
        }
    };

    float acc[2][4];
    #pragma unroll
    for (int nt = 0; nt < 2; ++nt)
        #pragma unroll
        for (int i = 0; i < 4; ++i) acc[nt][i] = 0.f;

    int ktiles = K >> 5;
    prefetch(0, 0); CP_COMMIT();
    prefetch(1, 1); CP_COMMIT();

    for (int kt = 0; kt < ktiles; ++kt) {
        int st = kt % 3;
        if (kt + 1 < ktiles) { CP_WAIT1(); } else { CP_WAIT0(); }
        __syncthreads();
        const hf* cA = sA + st*ASTG;
        const hf* cB = sB + st*HBSTG;

        #pragma unroll
        for (int kk = 0; kk < 32; kk += 16) {
            unsigned ah[4], al[4], bh[2][2];
            ldsm4(ah[0], ah[1], ah[2], ah[3], cA + a_row*40 + kk + a_col);
            ldsm4(al[0], al[1], al[2], al[3], cA + SM_ATILE + a_row*40 + kk + a_col);
            ldsm4(bh[0][0], bh[0][1], bh[1][0], bh[1][1], cB + (wn0 + b_row)*40 + kk + b_col);
            #pragma unroll
            for (int nt = 0; nt < 2; ++nt) {
                MMA_F16(acc[nt], ah, bh[nt]);
                MMA_F16(acc[nt], al, bh[nt]);
            }
        }
        if (kt + 2 < ktiles) { prefetch(kt + 2, (kt + 2) % 3); CP_COMMIT(); }
    }

    int g = lane >> 2;
    #pragma unroll
    for (int nt = 0; nt < 2; ++nt) {
        int c = col0 + wn0 + nt*8 + 2*t;
        int r0 = row0 + wm0 + g;
        *(float2*)(Cf + (size_t)r0*ldc + c)     = make_float2(acc[nt][0], acc[nt][1]);
        *(float2*)(Cf + (size_t)(r0+8)*ldc + c) = make_float2(acc[nt][2], acc[nt][3]);
    }
}

// ---------------- fused phase cumsum + complex exp -> spec fp16 hi/lo ----------------
__global__ void spec_k(const float* __restrict__ noise) {
    int b = blockIdx.x;
    int kk = threadIdx.x;
    int k = blockIdx.y*129 + kk;
    int chunk = threadIdx.y;
    __shared__ float cs[4][132];
    bool act = (kk < 129) && (k < NC);
    float freqpi = (float)k * (float)(M_PI/256.0);
    const float* xp = g_xout + (size_t)b*NF*TCL + (size_t)chunk*32*TCL;
    const float* np = noise  + (size_t)b*NF*NC + (size_t)chunk*32*NC + k;
    float s = 0.f;
    if (act) {
        const float* xq = xp + 2*k + 1;
        #pragma unroll 4
        for (int f = 0; f < 32; ++f)
            s = fmaf(fmaf(xq[(size_t)f*TCL], np[(size_t)f*NC], 1.f), freqpi, s);
    }
    cs[chunk][kk] = s;
    __syncthreads();
    if (!act) return;
    float p = 0.f;
    for (int c = 0; c < chunk; ++c) p += cs[c][kk];
    const float* xq = xp + 2*k;
    size_t o0 = (size_t)b*NF*TCL + (size_t)chunk*32*TCL + k;
    const float TWO_PI = 6.28318530717958647692f;
    const float INV_2PI = 0.15915494309189533577f;
    for (int f = 0; f < 32; ++f) {
        float mg = fabsf(xq[(size_t)f*TCL]);
        float ph = xq[(size_t)f*TCL + 1];
        float ns = np[(size_t)f*NC];
        p = fmaf(fmaf(ph, ns, 1.f), freqpi, p);
        float r = p - TWO_PI * rintf(p * INV_2PI);
        float sn, c;
        __sincosf(r, &sn, &c);
        hf h, l;
        size_t o = o0 + (size_t)f*TCL;
        split1h(mg * c,  h, l); g_sphH[o] = h;          g_splH[o] = l;
        split1h(mg * sn, h, l); g_sphH[o + IMOFF] = h;  g_splH[o + IMOFF] = l;
    }
}

// ---------------- overlap-add (from P/Q, hann applied here) + extract (fused) ----------------
__global__ void sig_ext_k(const float* __restrict__ times) {
    if (blockIdx.x < 4096) {
        int idx = blockIdx.x*256 + threadIdx.x;
        int b = idx >> 15;
        int s = idx & (NS-1);
        int f0 = s >> 8;
        int r = s & 255;
        const float PI256 = (float)(M_PI/256.0);
        const float* pq = g_pq + (size_t)(b*NF + f0)*NPQ2;
        float hann1 = 0.5f*(1.f - __cosf((float)r * PI256));
        float v = hann1 * (pq[r] - pq[NPQ + r]);
        if (f0 > 0) {
            const float* pq2 = g_pq + (size_t)(b*NF + f0 - 1)*NPQ2;
            int t = r + 256;
            float hann2 = 0.5f*(1.f - __cosf((float)t * PI256));
            float raw2;
            if (r == 0) raw2 = pq2[256] - pq2[NPQ + 256];
            else { int u = 256 - r; raw2 = pq2[u] + pq2[NPQ + u]; }
            v += hann2 * raw2;
        }
        g_sig[idx] = v;
    } else {
        int be = (blockIdx.x - 4096)*256 + threadIdx.x;
        if (be >= BB*NE) return;
        int cnt = 0;
        for (int f = 0; f < NF; ++f) {
            float v = times[(size_t)be*NF + f];
            if (v != 0.f) { g_evf[be*NF + cnt] = f; g_eva[be*NF + cnt] = v; ++cnt; }
        }
        g_evcnt[be] = cnt;
    }
}

// ---------------- sparse shift-add convolution ----------------
__global__ void conv_k(float* __restrict__ out) {
    int be = blockIdx.y;
    int b = be >> 4;
    int t = (blockIdx.x*blockDim.x + threadIdx.x) * 4;
    int cnt = g_evcnt[be];
    const float* sg = g_sig + (size_t)b*NS;
    float4 acc = make_float4(0.f, 0.f, 0.f, 0.f);
    for (int j = 0; j < cnt; ++j) {
        int f = g_evf[be*NF + j];
        float a = g_eva[be*NF + j];
        int s = t - (f << 8);
        if (s >= 0) {
            float4 v = *(const float4*)(sg + s);
            acc.x = fmaf(a, v.x, acc.x);
            acc.y = fmaf(a, v.y, acc.y);
            acc.z = fmaf(a, v.z, acc.z);
            acc.w = fmaf(a, v.w, acc.w);
        }
    }
    *(float4*)(out + (size_t)be*NS + t) = acc;
}

// ---------------- launch ----------------
extern "C" void kernel_launch(void* const* d_in, const int* in_sizes, int n_in,
                              void* d_out, int out_size) {
    const float* param  = (const float*)d_in[0];
    const float* times  = (const float*)d_in[1];
    const float* noise  = (const float*)d_in[2];
    const float* pos    = (const float*)d_in[3];
    const float* proj_w = (const float*)d_in[4];
    const float* proj_b = (const float*)d_in[5];
    const float* w0     = (const float*)d_in[6];
    const float* b0     = (const float*)d_in[7];
    const float* w1     = (const float*)d_in[8];
    const float* b1     = (const float*)d_in[9];
    const float* w2     = (const float*)d_in[10];
    const float* b2     = (const float*)d_in[11];
    const float* w_out  = (const float*)d_in[12];
    const float* b_out  = (const float*)d_in[13];
    float* out = (float*)d_out;

    float *xout, *pq, *bout;
    bf *a0h,*a0l,*a1h,*a1l,*w0h,*w0l,*w1h,*w1l,*w2h,*w2l,*woh,*wol;
    hf *basPQ,*sphH,*splH;
    cudaGetSymbolAddress((void**)&xout, g_xout);
    cudaGetSymbolAddress((void**)&pq,   g_pq);
    cudaGetSymbolAddress((void**)&bout, g_bout);
    cudaGetSymbolAddress((void**)&a0h, g_a0h); cudaGetSymbolAddress((void**)&a0l, g_a0l);
    cudaGetSymbolAddress((void**)&a1h, g_a1h); cudaGetSymbolAddress((void**)&a1l, g_a1l);
    cudaGetSymbolAddress((void**)&w0h, g_w0h); cudaGetSymbolAddress((void**)&w0l, g_w0l);
    cudaGetSymbolAddress((void**)&w1h, g_w1h); cudaGetSymbolAddress((void**)&w1l, g_w1l);
    cudaGetSymbolAddress((void**)&w2h, g_w2h); cudaGetSymbolAddress((void**)&w2l, g_w2l);
    cudaGetSymbolAddress((void**)&woh, g_woh); cudaGetSymbolAddress((void**)&wol, g_wol);
    cudaGetSymbolAddress((void**)&basPQ, g_basPQ);
    cudaGetSymbolAddress((void**)&sphH, g_sphH); cudaGetSymbolAddress((void**)&splH, g_splH);

    static bool attr_done = false;
    if (!attr_done) {
        cudaFuncSetAttribute(gemm7_k<true,  true,  true >, cudaFuncAttributeMaxDynamicSharedMemorySize, SMEM_BYTES);
        cudaFuncSetAttribute(gemm7_k<false, true,  false>, cudaFuncAttributeMaxDynamicSharedMemorySize, SMEM_BYTES);
        cudaFuncSetAttribute(gemmh_k, cudaFuncAttributeMaxDynamicSharedMemorySize, SMEMH_BYTES);
        attr_done = true;
    }

    prep_k<<<(PREP_TOTAL + 255)/256, 256>>>(w0, w1, w2, w_out, b_out);
    proj_addpos_k<<<BB, 256>>>(param, proj_w, proj_b, pos);

    // MLP layers (bf16 3-term); BN=32 tiles -> grid.x = N/32
    gemm7_k<true, true, true><<<dim3(8, 64), 256, SMEM_BYTES>>>(
        a0h, a0l, w0h, w0l, b0, (float*)0, a1h, a1l, NROWS, CH, CH, CH, CH, CH);
    gemm7_k<true, true, true><<<dim3(8, 64), 256, SMEM_BYTES>>>(
        a1h, a1l, w1h, w1l, b1, (float*)0, a0h, a0l, NROWS, CH, CH, CH, CH, CH);
    gemm7_k<true, true, true><<<dim3(8, 64), 256, SMEM_BYTES>>>(
        a0h, a0l, w2h, w2l, b2, (float*)0, a1h, a1l, NROWS, CH, CH, CH, CH, CH);
    // out layer (bf16 3-term): padded N=576, fp32 out, ldc=TCL
    gemm7_k<false, true, false><<<dim3(18, 64), 256, SMEM_BYTES>>>(
        a1h, a1l, woh, wol, bout, xout, (bf*)0, (bf*)0, NROWS, NWO, CH, CH, CH, TCL);

    spec_k<<<dim3(BB, 2), dim3(132, 4)>>>(noise);

    // P|Q = spec_{re|im} @ {cos|sin}Basis^T (fp16 2-term; K=288, N=640)
    gemmh_k<<<dim3(20, 64), 256, SMEMH_BYTES>>>(
        sphH, splH, basPQ, pq, KPQ, TCL, KPQ, NPQ2);

    sig_ext_k<<<4098, 256>>>(times);
    conv_k<<<dim3(NS/1024, BB*NE), 256>>>(out);
}

// round 16
// speedup vs baseline: 1.1797x; 1.1797x over previous
#include <cuda_runtime.h>
#include <cuda_bf16.h>
#include <cuda_fp16.h>
#include <math.h>

#define BB 32
#define CTX 128
#define NF 128
#define NS 32768
#define NE 16
#define CH 256
#define WIN 512
#define NC 257
#define TC 514
#define TCL 576              // padded ld for xout/spec (re at 0, im at 288)
#define IMOFF 288
#define KPQ 288              // K for P/Q GEMM (257 padded; 9 K-tiles of 32)
#define NPQ 320              // padded t-range per half (5 x 64 N-blocks)
#define NPQ2 640
#define NROWS (BB*NF)        // 4096
#define NWO 576              // padded w_out rows

typedef __nv_bfloat16 bf;
typedef __half hf;

// ---------------- static scratch (zero-initialized at load; pads stay 0) ----------------
__device__ float g_xout[NROWS*TCL];
__device__ float g_pq[NROWS*NPQ2];                 // P cols [0,320), Q cols [320,640)
__device__ float g_sig[BB*NS];
__device__ int   g_evcnt[BB*NE];
__device__ int   g_evf[BB*NE*NF];
__device__ float g_eva[BB*NE*NF];
__device__ float g_bout[NWO];
// bf16 hi/lo operands (MLP path, 3-term split)
__device__ bf g_a0h[NROWS*CH], g_a0l[NROWS*CH];
__device__ bf g_a1h[NROWS*CH], g_a1l[NROWS*CH];
__device__ bf g_w0h[CH*CH],  g_w0l[CH*CH];
__device__ bf g_w1h[CH*CH],  g_w1l[CH*CH];
__device__ bf g_w2h[CH*CH],  g_w2l[CH*CH];
__device__ bf g_woh[NWO*CH], g_wol[NWO*CH];
// fp16 operands (irfft path): basis rows [0,320)=cos, [320,640)=sin; spec hi/lo
__device__ hf g_basPQ[NPQ2*KPQ];
__device__ hf g_sphH[NROWS*TCL], g_splH[NROWS*TCL];

// ---------------- helpers ----------------
__device__ __forceinline__ void split1(float v, bf& h, bf& l) {
    h = __float2bfloat16(v);
    l = __float2bfloat16(v - __bfloat162float(h));
}
__device__ __forceinline__ void split1h(float v, hf& h, hf& l) {
    h = __float2half(v);
    l = __float2half(v - __half2float(h));
}
__device__ __forceinline__ void cp16(void* dst, const void* src) {
    unsigned d = (unsigned)__cvta_generic_to_shared(dst);
    asm volatile("cp.async.ca.shared.global [%0], [%1], 16;" :: "r"(d), "l"(src));
}
#define CP_COMMIT() asm volatile("cp.async.commit_group;")
#define CP_WAIT1()  asm volatile("cp.async.wait_group 1;")
#define CP_WAIT0()  asm volatile("cp.async.wait_group 0;")

__device__ __forceinline__ void ldsm4(unsigned& r0, unsigned& r1, unsigned& r2, unsigned& r3,
                                      const void* p) {
    unsigned a = (unsigned)__cvta_generic_to_shared(p);
    asm volatile("ldmatrix.sync.aligned.m8n8.x4.shared.b16 {%0,%1,%2,%3}, [%4];"
                 : "=r"(r0), "=r"(r1), "=r"(r2), "=r"(r3) : "r"(a));
}

#define MMA_BF16(d, a, b) \
    asm volatile("mma.sync.aligned.m16n8k16.row.col.f32.bf16.bf16.f32 " \
                 "{%0,%1,%2,%3},{%4,%5,%6,%7},{%8,%9},{%0,%1,%2,%3};" \
                 : "+f"(d[0]), "+f"(d[1]), "+f"(d[2]), "+f"(d[3]) \
                 : "r"(a[0]), "r"(a[1]), "r"(a[2]), "r"(a[3]), "r"(b[0]), "r"(b[1]))

#define MMA_F16(d, a, b) \
    asm volatile("mma.sync.aligned.m16n8k16.row.col.f32.f16.f16.f32 " \
                 "{%0,%1,%2,%3},{%4,%5,%6,%7},{%8,%9},{%0,%1,%2,%3};" \
                 : "+f"(d[0]), "+f"(d[1]), "+f"(d[2]), "+f"(d[3]) \
                 : "r"(a[0]), "r"(a[1]), "r"(a[2]), "r"(a[3]), "r"(b[0]), "r"(b[1]))

// ---------------- prep: P/Q basis (fp16) + all weight converts + padded bias ----------------
#define NB_BAS (NPQ2*KPQ)
#define NV_W   (CH*CH/4)
#define NV_WO  (TC*CH/4)
#define PREP_TOTAL (NB_BAS + 3*NV_W + NV_WO + TC)
__global__ void prep_k(const float* __restrict__ w0, const float* __restrict__ w1,
                       const float* __restrict__ w2, const float* __restrict__ wo,
                       const float* __restrict__ b_out) {
    int idx = blockIdx.x*blockDim.x + threadIdx.x;
    if (idx < NB_BAS) {
        int row = idx / KPQ;
        int k = idx - row*KPQ;
        bool is_sin = (row >= NPQ);
        int t = is_sin ? row - NPQ : row;
        float val = 0.f;
        if (k < NC) {
            int m = (k * t) & (WIN - 1);
            float theta = (float)m * (float)(M_PI/256.0);
            float w = (k == 0 || k == NC-1) ? 1.f : 2.f;
            float v = is_sin ? sinf(theta) : cosf(theta);
            val = v * w * (1.f/512.f);
        }
        g_basPQ[idx] = __float2half(val);
        return;
    }
    int r = idx - NB_BAS;
    const float* src; bf* hi; bf* lo;
    if      (r < NV_W)          { src = w0; hi = g_w0h; lo = g_w0l; }
    else if (r < 2*NV_W)        { src = w1; hi = g_w1h; lo = g_w1l; r -= NV_W; }
    else if (r < 3*NV_W)        { src = w2; hi = g_w2h; lo = g_w2l; r -= 2*NV_W; }
    else if (r < 3*NV_W+NV_WO)  { src = wo; hi = g_woh; lo = g_wol; r -= 3*NV_W; }
    else if (r < 3*NV_W+NV_WO+TC) { g_bout[r - 3*NV_W - NV_WO] = b_out[r - 3*NV_W - NV_WO]; return; }
    else return;
    int i = r*4;
    float4 v = *(const float4*)(src + i);
    bf h0,h1,h2,h3,l0,l1,l2,l3;
    split1(v.x,h0,l0); split1(v.y,h1,l1); split1(v.z,h2,l2); split1(v.w,h3,l3);
    __nv_bfloat162 hh0 = {h0,h1}, hh1 = {h2,h3}, ll0 = {l0,l1}, ll1 = {l2,l3};
    *(uint2*)(hi + i) = make_uint2(*(unsigned*)&hh0, *(unsigned*)&hh1);
    *(uint2*)(lo + i) = make_uint2(*(unsigned*)&ll0, *(unsigned*)&ll1);
}

// ---------------- fused proj + addpos + split ----------------
__global__ void proj_addpos_k(const float* __restrict__ param, const float* __restrict__ proj_w,
                              const float* __restrict__ proj_b, const float* __restrict__ pos) {
    int b = blockIdx.x;
    int c = threadIdx.x;                    // 256
    __shared__ float pr[CTX];
    __shared__ float bs[CH];
    if (c < CTX) pr[c] = param[b*CTX + c];
    __syncthreads();
    float acc = proj_b[c];
    const float* wr = proj_w + (size_t)c*CTX;
    #pragma unroll 8
    for (int k = 0; k < CTX; ++k) acc = fmaf(pr[k], wr[k], acc);
    bs[c] = acc;
    __syncthreads();
    int c4 = (c & 63) * 4;
    int f0 = c >> 6;
    float4 vb = *(const float4*)&bs[c4];
    #pragma unroll 4
    for (int i = 0; i < 32; ++i) {
        int f = f0 + i*4;
        float4 vp = *(const float4*)(pos + (size_t)f*CH + c4);
        float4 v = make_float4(vb.x+vp.x, vb.y+vp.y, vb.z+vp.z, vb.w+vp.w);
        bf h0,h1,h2,h3,l0,l1,l2,l3;
        split1(v.x,h0,l0); split1(v.y,h1,l1); split1(v.z,h2,l2); split1(v.w,h3,l3);
        __nv_bfloat162 hh0 = {h0,h1}, hh1 = {h2,h3}, ll0 = {l0,l1}, ll1 = {l2,l3};
        size_t o = (size_t)(b*NF + f)*CH + c4;
        *(uint2*)(g_a0h + o) = make_uint2(*(unsigned*)&hh0, *(unsigned*)&hh1);
        *(uint2*)(g_a0l + o) = make_uint2(*(unsigned*)&ll0, *(unsigned*)&ll1);
    }
}

// ---------------- bf16 3-term GEMM (R14 geometry: BM=64, BN=64, BK=32, 256 thr, 3-stage)
// Split accumulators: acch (ah*bh), accl (ah*bl + al*bh) -> max MMA chain 2, 8 indep chains.
#define SM_TILE (64*40)
#define SM_STAGE (2*SM_TILE)
#define SM_HALF (3*SM_STAGE)
#define SMEM_BYTES (2*SM_HALF*2)

template<bool RELU, bool BIAS, bool SPLITOUT>
__global__ void __launch_bounds__(256) gemm7_k(
    const bf* __restrict__ Ah, const bf* __restrict__ Al,
    const bf* __restrict__ Wh, const bf* __restrict__ Wl,
    const float* __restrict__ bias,
    float* __restrict__ Cf, bf* __restrict__ Ch, bf* __restrict__ Cl,
    int M, int N, int K, int lda, int ldw, int ldc)
{
    extern __shared__ __align__(16) bf sm[];
    bf* sA = sm;
    bf* sB = sm + SM_HALF;

    int tid = threadIdx.x;
    int row0 = blockIdx.y * 64;
    int col0 = blockIdx.x * 64;

    int lrow = tid >> 2;
    int lch  = (tid & 3) * 8;

    int wid  = tid >> 5;
    int lane = tid & 31;
    int wm0 = (wid >> 1) * 16;
    int wn0 = (wid & 1) * 32;
    int t = lane & 3;

    int q  = lane >> 3;
    int r8 = lane & 7;
    int a_row = wm0 + ((q & 1) << 3) + r8;
    int a_col = (q >> 1) << 3;
    int b_row = ((q >> 1) << 3) + r8;
    int b_col = (q & 1) << 3;

    auto prefetch = [&](int kt, int st) {
        int gk = kt*32 + lch;
        bf* pa = sA + st*SM_STAGE + lrow*40 + lch;
        bf* pb = sB + st*SM_STAGE + lrow*40 + lch;
        cp16(pa,           Ah + (size_t)(row0+lrow)*lda + gk);
        cp16(pa + SM_TILE, Al + (size_t)(row0+lrow)*lda + gk);
        cp16(pb,           Wh + (size_t)(col0+lrow)*ldw + gk);
        cp16(pb + SM_TILE, Wl + (size_t)(col0+lrow)*ldw + gk);
    };

    float acch[4][4], accl[4][4];
    #pragma unroll
    for (int nt = 0; nt < 4; ++nt)
        #pragma unroll
        for (int i = 0; i < 4; ++i) { acch[nt][i] = 0.f; accl[nt][i] = 0.f; }

    int ktiles = K >> 5;
    prefetch(0, 0); CP_COMMIT();
    prefetch(1, 1); CP_COMMIT();

    for (int kt = 0; kt < ktiles; ++kt) {
        int st = kt % 3;
        if (kt + 1 < ktiles) { CP_WAIT1(); } else { CP_WAIT0(); }
        __syncthreads();
        const bf* cA = sA + st*SM_STAGE;
        const bf* cB = sB + st*SM_STAGE;

        #pragma unroll
        for (int kk = 0; kk < 32; kk += 16) {
            unsigned ah[4], al[4], bh[4][2], bl[4][2];
            ldsm4(ah[0], ah[1], ah[2], ah[3], cA + a_row*40 + kk + a_col);
            ldsm4(al[0], al[1], al[2], al[3], cA + SM_TILE + a_row*40 + kk + a_col);
            ldsm4(bh[0][0], bh[0][1], bh[1][0], bh[1][1], cB + (wn0      + b_row)*40 + kk + b_col);
            ldsm4(bh[2][0], bh[2][1], bh[3][0], bh[3][1], cB + (wn0 + 16 + b_row)*40 + kk + b_col);
            ldsm4(bl[0][0], bl[0][1], bl[1][0], bl[1][1], cB + SM_TILE + (wn0      + b_row)*40 + kk + b_col);
            ldsm4(bl[2][0], bl[2][1], bl[3][0], bl[3][1], cB + SM_TILE + (wn0 + 16 + b_row)*40 + kk + b_col);
            #pragma unroll
            for (int nt = 0; nt < 4; ++nt) {
                MMA_BF16(acch[nt], ah, bh[nt]);   // chain depth 1
                MMA_BF16(accl[nt], ah, bl[nt]);   // chain depth 2 on accl
                MMA_BF16(accl[nt], al, bh[nt]);
            }
        }
        if (kt + 2 < ktiles) { prefetch(kt + 2, (kt + 2) % 3); CP_COMMIT(); }
    }

    int g = lane >> 2;
    #pragma unroll
    for (int nt = 0; nt < 4; ++nt) {
        int c = col0 + wn0 + nt*8 + 2*t;
        float b0 = BIAS ? bias[c]   : 0.f;
        float b1 = BIAS ? bias[c+1] : 0.f;
        int r0 = row0 + wm0 + g;
        float v[4] = {acch[nt][0] + accl[nt][0] + b0, acch[nt][1] + accl[nt][1] + b1,
                      acch[nt][2] + accl[nt][2] + b0, acch[nt][3] + accl[nt][3] + b1};
        if (RELU) {
            #pragma unroll
            for (int qq = 0; qq < 4; ++qq) v[qq] = (v[qq] > 0.f) ? v[qq] : 0.2f*v[qq];
        }
        if (SPLITOUT) {
            bf h0,h1,h2,h3,l0,l1,l2,l3;
            split1(v[0],h0,l0); split1(v[1],h1,l1);
            split1(v[2],h2,l2); split1(v[3],h3,l3);
            __nv_bfloat162 hA = {h0,h1}, hB = {h2,h3}, lA = {l0,l1}, lB = {l2,l3};
            *(__nv_bfloat162*)(Ch + (size_t)r0*ldc + c)     = hA;
            *(__nv_bfloat162*)(Ch + (size_t)(r0+8)*ldc + c) = hB;
            *(__nv_bfloat162*)(Cl + (size_t)r0*ldc + c)     = lA;
            *(__nv_bfloat162*)(Cl + (size_t)(r0+8)*ldc + c) = lB;
        } else {
            *(float2*)(Cf + (size_t)r0*ldc + c)     = make_float2(v[0], v[1]);
            *(float2*)(Cf + (size_t)(r0+8)*ldc + c) = make_float2(v[2], v[3]);
        }
    }
}

// ---------------- fp16 2-term GEMM (P/Q irfft path): R14 geometry + split accumulators ----------------
#define HSM_TILE (64*40)
#define HA_STAGE (2*HSM_TILE)
#define HA_TOTAL (3*HA_STAGE)
#define HB_STAGE (HSM_TILE)
#define SMEMH_BYTES ((HA_TOTAL + 3*HB_STAGE)*2)

__global__ void __launch_bounds__(256) gemmh_k(
    const hf* __restrict__ Ah0, const hf* __restrict__ Al0,
    const hf* __restrict__ W,
    float* __restrict__ Cf,
    int K, int lda, int ldw, int ldc)
{
    extern __shared__ __align__(16) hf smh[];
    hf* sA = smh;
    hf* sB = smh + HA_TOTAL;

    int tid = threadIdx.x;
    int row0 = blockIdx.y * 64;
    int col0 = blockIdx.x * 64;
    const hf* Ah = (col0 >= NPQ) ? Ah0 + IMOFF : Ah0;
    const hf* Al = (col0 >= NPQ) ? Al0 + IMOFF : Al0;

    int lrow = tid >> 2;
    int lch  = (tid & 3) * 8;

    int wid  = tid >> 5;
    int lane = tid & 31;
    int wm0 = (wid >> 1) * 16;
    int wn0 = (wid & 1) * 32;
    int t = lane & 3;

    int q  = lane >> 3;
    int r8 = lane & 7;
    int a_row = wm0 + ((q & 1) << 3) + r8;
    int a_col = (q >> 1) << 3;
    int b_row = ((q >> 1) << 3) + r8;
    int b_col = (q & 1) << 3;

    auto prefetch = [&](int kt, int st) {
        int gk = kt*32 + lch;
        hf* pa = sA + st*HA_STAGE + lrow*40 + lch;
        hf* pb = sB + st*HB_STAGE + lrow*40 + lch;
        cp16(pa,            Ah + (size_t)(row0+lrow)*lda + gk);
        cp16(pa + HSM_TILE, Al + (size_t)(row0+lrow)*lda + gk);
        cp16(pb,            W  + (size_t)(col0+lrow)*ldw + gk);
    };

    float acch[4][4], accl[4][4];
    #pragma unroll
    for (int nt = 0; nt < 4; ++nt)
        #pragma unroll
        for (int i = 0; i < 4; ++i) { acch[nt][i] = 0.f; accl[nt][i] = 0.f; }

    int ktiles = K >> 5;
    prefetch(0, 0); CP_COMMIT();
    prefetch(1, 1); CP_COMMIT();

    for (int kt = 0; kt < ktiles; ++kt) {
        int st = kt % 3;
        if (kt + 1 < ktiles) { CP_WAIT1(); } else { CP_WAIT0(); }
        __syncthreads();
        const hf* cA = sA + st*HA_STAGE;
        const hf* cB = sB + st*HB_STAGE;

        #pragma unroll
        for (int kk = 0; kk < 32; kk += 16) {
            unsigned ah[4], al[4], bh[4][2];
            ldsm4(ah[0], ah[1], ah[2], ah[3], cA + a_row*40 + kk + a_col);
            ldsm4(al[0], al[1], al[2], al[3], cA + HSM_TILE + a_row*40 + kk + a_col);
            ldsm4(bh[0][0], bh[0][1], bh[1][0], bh[1][1], cB + (wn0      + b_row)*40 + kk + b_col);
            ldsm4(bh[2][0], bh[2][1], bh[3][0], bh[3][1], cB + (wn0 + 16 + b_row)*40 + kk + b_col);
            #pragma unroll
            for (int nt = 0; nt < 4; ++nt) {
                MMA_F16(acch[nt], ah, bh[nt]);    // both chains depth 1
                MMA_F16(accl[nt], al, bh[nt]);
            }
        }
        if (kt + 2 < ktiles) { prefetch(kt + 2, (kt + 2) % 3); CP_COMMIT(); }
    }

    int g = lane >> 2;
    #pragma unroll
    for (int nt = 0; nt < 4; ++nt) {
        int c = col0 + wn0 + nt*8 + 2*t;
        int r0 = row0 + wm0 + g;
        *(float2*)(Cf + (size_t)r0*ldc + c) =
            make_float2(acch[nt][0] + accl[nt][0], acch[nt][1] + accl[nt][1]);
        *(float2*)(Cf + (size_t)(r0+8)*ldc + c) =
            make_float2(acch[nt][2] + accl[nt][2], acch[nt][3] + accl[nt][3]);
    }
}

// ---------------- fused phase cumsum + complex exp -> spec fp16 hi/lo ----------------
// grid (BB, 4); block (66, 8): k = by*66 + tx; chunk = ty (16 frames each). 128 blocks.
__global__ void spec_k(const float* __restrict__ noise) {
    int b = blockIdx.x;
    int kk = threadIdx.x;                       // 0..65
    int k = blockIdx.y*66 + kk;                 // covers 0..263
    int chunk = threadIdx.y;                    // 0..7
    __shared__ float cs[8][66];
    bool act = (k < NC);
    float freqpi = (float)k * (float)(M_PI/256.0);
    const float* xp = g_xout + (size_t)b*NF*TCL + (size_t)chunk*16*TCL;
    const float* np = noise  + (size_t)b*NF*NC + (size_t)chunk*16*NC + k;
    float s = 0.f;
    if (act) {
        const float* xq = xp + 2*k + 1;
        #pragma unroll 4
        for (int f = 0; f < 16; ++f)
            s = fmaf(fmaf(xq[(size_t)f*TCL], np[(size_t)f*NC], 1.f), freqpi, s);
    }
    cs[chunk][kk] = s;
    __syncthreads();
    if (!act) return;
    float p = 0.f;
    for (int c = 0; c < chunk; ++c) p += cs[c][kk];
    const float* xq = xp + 2*k;
    size_t o0 = (size_t)b*NF*TCL + (size_t)chunk*16*TCL + k;
    const float TWO_PI = 6.28318530717958647692f;
    const float INV_2PI = 0.15915494309189533577f;
    for (int f = 0; f < 16; ++f) {
        float mg = fabsf(xq[(size_t)f*TCL]);
        float ph = xq[(size_t)f*TCL + 1];
        float ns = np[(size_t)f*NC];
        p = fmaf(fmaf(ph, ns, 1.f), freqpi, p);
        float r = p - TWO_PI * rintf(p * INV_2PI);
        float sn, c;
        __sincosf(r, &sn, &c);
        hf h, l;
        size_t o = o0 + (size_t)f*TCL;
        split1h(mg * c,  h, l); g_sphH[o] = h;          g_splH[o] = l;
        split1h(mg * sn, h, l); g_sphH[o + IMOFF] = h;  g_splH[o + IMOFF] = l;
    }
}

// ---------------- overlap-add (from P/Q, hann applied here) + extract (fused) ----------------
__global__ void sig_ext_k(const float* __restrict__ times) {
    if (blockIdx.x < 4096) {
        int idx = blockIdx.x*256 + threadIdx.x;
        int b = idx >> 15;
        int s = idx & (NS-1);
        int f0 = s >> 8;
        int r = s & 255;
        const float PI256 = (float)(M_PI/256.0);
        const float* pq = g_pq + (size_t)(b*NF + f0)*NPQ2;
        float hann1 = 0.5f*(1.f - __cosf((float)r * PI256));
        float v = hann1 * (pq[r] - pq[NPQ + r]);
        if (f0 > 0) {
            const float* pq2 = g_pq + (size_t)(b*NF + f0 - 1)*NPQ2;
            int t = r + 256;
            float hann2 = 0.5f*(1.f - __cosf((float)t * PI256));
            float raw2;
            if (r == 0) raw2 = pq2[256] - pq2[NPQ + 256];
            else { int u = 256 - r; raw2 = pq2[u] + pq2[NPQ + u]; }
            v += hann2 * raw2;
        }
        g_sig[idx] = v;
    } else {
        int be = (blockIdx.x - 4096)*256 + threadIdx.x;
        if (be >= BB*NE) return;
        int cnt = 0;
        for (int f = 0; f < NF; ++f) {
            float v = times[(size_t)be*NF + f];
            if (v != 0.f) { g_evf[be*NF + cnt] = f; g_eva[be*NF + cnt] = v; ++cnt; }
        }
        g_evcnt[be] = cnt;
    }
}

// ---------------- sparse shift-add convolution ----------------
__global__ void conv_k(float* __restrict__ out) {
    int be = blockIdx.y;
    int b = be >> 4;
    int t = (blockIdx.x*blockDim.x + threadIdx.x) * 4;
    int cnt = g_evcnt[be];
    const float* sg = g_sig + (size_t)b*NS;
    float4 acc = make_float4(0.f, 0.f, 0.f, 0.f);
    for (int j = 0; j < cnt; ++j) {
        int f = g_evf[be*NF + j];
        float a = g_eva[be*NF + j];
        int s = t - (f << 8);
        if (s >= 0) {
            float4 v = *(const float4*)(sg + s);
            acc.x = fmaf(a, v.x, acc.x);
            acc.y = fmaf(a, v.y, acc.y);
            acc.z = fmaf(a, v.z, acc.z);
            acc.w = fmaf(a, v.w, acc.w);
        }
    }
    *(float4*)(out + (size_t)be*NS + t) = acc;
}

// ---------------- launch ----------------
extern "C" void kernel_launch(void* const* d_in, const int* in_sizes, int n_in,
                              void* d_out, int out_size) {
    const float* param  = (const float*)d_in[0];
    const float* times  = (const float*)d_in[1];
    const float* noise  = (const float*)d_in[2];
    const float* pos    = (const float*)d_in[3];
    const float* proj_w = (const float*)d_in[4];
    const float* proj_b = (const float*)d_in[5];
    const float* w0     = (const float*)d_in[6];
    const float* b0     = (const float*)d_in[7];
    const float* w1     = (const float*)d_in[8];
    const float* b1     = (const float*)d_in[9];
    const float* w2     = (const float*)d_in[10];
    const float* b2     = (const float*)d_in[11];
    const float* w_out  = (const float*)d_in[12];
    const float* b_out  = (const float*)d_in[13];
    float* out = (float*)d_out;

    float *xout, *pq, *bout;
    bf *a0h,*a0l,*a1h,*a1l,*w0h,*w0l,*w1h,*w1l,*w2h,*w2l,*woh,*wol;
    hf *basPQ,*sphH,*splH;
    cudaGetSymbolAddress((void**)&xout, g_xout);
    cudaGetSymbolAddress((void**)&pq,   g_pq);
    cudaGetSymbolAddress((void**)&bout, g_bout);
    cudaGetSymbolAddress((void**)&a0h, g_a0h); cudaGetSymbolAddress((void**)&a0l, g_a0l);
    cudaGetSymbolAddress((void**)&a1h, g_a1h); cudaGetSymbolAddress((void**)&a1l, g_a1l);
    cudaGetSymbolAddress((void**)&w0h, g_w0h); cudaGetSymbolAddress((void**)&w0l, g_w0l);
    cudaGetSymbolAddress((void**)&w1h, g_w1h); cudaGetSymbolAddress((void**)&w1l, g_w1l);
    cudaGetSymbolAddress((void**)&w2h, g_w2h); cudaGetSymbolAddress((void**)&w2l, g_w2l);
    cudaGetSymbolAddress((void**)&woh, g_woh); cudaGetSymbolAddress((void**)&wol, g_wol);
    cudaGetSymbolAddress((void**)&basPQ, g_basPQ);
    cudaGetSymbolAddress((void**)&sphH, g_sphH); cudaGetSymbolAddress((void**)&splH, g_splH);

    static bool attr_done = false;
    if (!attr_done) {
        cudaFuncSetAttribute(gemm7_k<true,  true,  true >, cudaFuncAttributeMaxDynamicSharedMemorySize, SMEM_BYTES);
        cudaFuncSetAttribute(gemm7_k<false, true,  false>, cudaFuncAttributeMaxDynamicSharedMemorySize, SMEM_BYTES);
        cudaFuncSetAttribute(gemmh_k, cudaFuncAttributeMaxDynamicSharedMemorySize, SMEMH_BYTES);
        attr_done = true;
    }

    prep_k<<<(PREP_TOTAL + 255)/256, 256>>>(w0, w1, w2, w_out, b_out);
    proj_addpos_k<<<BB, 256>>>(param, proj_w, proj_b, pos);

    // MLP layers (bf16 3-term), R14 grids
    gemm7_k<true, true, true><<<dim3(4, 64), 256, SMEM_BYTES>>>(
        a0h, a0l, w0h, w0l, b0, (float*)0, a1h, a1l, NROWS, CH, CH, CH, CH, CH);
    gemm7_k<true, true, true><<<dim3(4, 64), 256, SMEM_BYTES>>>(
        a1h, a1l, w1h, w1l, b1, (float*)0, a0h, a0l, NROWS, CH, CH, CH, CH, CH);
    gemm7_k<true, true, true><<<dim3(4, 64), 256, SMEM_BYTES>>>(
        a0h, a0l, w2h, w2l, b2, (float*)0, a1h, a1l, NROWS, CH, CH, CH, CH, CH);
    // out layer (bf16 3-term): padded N=576, fp32 out, ldc=TCL
    gemm7_k<false, true, false><<<dim3(9, 64), 256, SMEM_BYTES>>>(
        a1h, a1l, woh, wol, bout, xout, (bf*)0, (bf*)0, NROWS, NWO, CH, CH, CH, TCL);

    spec_k<<<dim3(BB, 4), dim3(66, 8)>>>(noise);

    // P|Q = spec_{re|im} @ {cos|sin}Basis^T (fp16 2-term; K=288, N=640)
    gemmh_k<<<dim3(10, 64), 256, SMEMH_BYTES>>>(
        sphH, splH, basPQ, pq, KPQ, TCL, KPQ, NPQ2);

    sig_ext_k<<<4098, 256>>>(times);
    conv_k<<<dim3(NS/1024, BB*NE), 256>>>(out);
}

// round 17
// speedup vs baseline: 1.2269x; 1.0400x over previous
#include <cuda_runtime.h>
#include <cuda_bf16.h>
#include <cuda_fp16.h>
#include <math.h>

#define BB 32
#define CTX 128
#define NF 128
#define NS 32768
#define NE 16
#define CH 256
#define WIN 512
#define NC 257
#define TC 514
#define TCL 576              // padded ld for xout/spec (re at 0, im at 288)
#define IMOFF 288
#define KPQ 288              // K for P/Q GEMM (257 padded; 9 K-tiles of 32)
#define NPQ 320              // padded t-range per half (5 x 64 N-blocks)
#define NPQ2 640
#define NROWS (BB*NF)        // 4096
#define NWO 576              // padded w_out rows

typedef __nv_bfloat16 bf;
typedef __half hf;

// ---------------- static scratch (zero-initialized at load; pads stay 0) ----------------
__device__ float g_xout[NROWS*TCL];
__device__ float g_pq[NROWS*NPQ2];                 // P cols [0,320), Q cols [320,640)
__device__ float g_sig[BB*NS];
__device__ int   g_evcnt[BB*NE];
__device__ int   g_evf[BB*NE*NF];
__device__ float g_eva[BB*NE*NF];
__device__ float g_bout[NWO];
// bf16 hi/lo operands (MLP path, 3-term split)
__device__ bf g_a0h[NROWS*CH], g_a0l[NROWS*CH];
__device__ bf g_a1h[NROWS*CH], g_a1l[NROWS*CH];
__device__ bf g_w0h[CH*CH],  g_w0l[CH*CH];
__device__ bf g_w1h[CH*CH],  g_w1l[CH*CH];
__device__ bf g_w2h[CH*CH],  g_w2l[CH*CH];
__device__ bf g_woh[NWO*CH], g_wol[NWO*CH];
// fp16 operands (irfft path): basis rows [0,320)=cos, [320,640)=sin; spec single fp16
__device__ hf g_basPQ[NPQ2*KPQ];
__device__ hf g_sphH[NROWS*TCL];

// ---------------- helpers ----------------
__device__ __forceinline__ void split1(float v, bf& h, bf& l) {
    h = __float2bfloat16(v);
    l = __float2bfloat16(v - __bfloat162float(h));
}
__device__ __forceinline__ void cp16(void* dst, const void* src) {
    unsigned d = (unsigned)__cvta_generic_to_shared(dst);
    asm volatile("cp.async.ca.shared.global [%0], [%1], 16;" :: "r"(d), "l"(src));
}
#define CP_COMMIT() asm volatile("cp.async.commit_group;")
#define CP_WAIT1()  asm volatile("cp.async.wait_group 1;")
#define CP_WAIT0()  asm volatile("cp.async.wait_group 0;")

__device__ __forceinline__ void ldsm4(unsigned& r0, unsigned& r1, unsigned& r2, unsigned& r3,
                                      const void* p) {
    unsigned a = (unsigned)__cvta_generic_to_shared(p);
    asm volatile("ldmatrix.sync.aligned.m8n8.x4.shared.b16 {%0,%1,%2,%3}, [%4];"
                 : "=r"(r0), "=r"(r1), "=r"(r2), "=r"(r3) : "r"(a));
}

#define MMA_BF16(d, a, b) \
    asm volatile("mma.sync.aligned.m16n8k16.row.col.f32.bf16.bf16.f32 " \
                 "{%0,%1,%2,%3},{%4,%5,%6,%7},{%8,%9},{%0,%1,%2,%3};" \
                 : "+f"(d[0]), "+f"(d[1]), "+f"(d[2]), "+f"(d[3]) \
                 : "r"(a[0]), "r"(a[1]), "r"(a[2]), "r"(a[3]), "r"(b[0]), "r"(b[1]))

#define MMA_F16(d, a, b) \
    asm volatile("mma.sync.aligned.m16n8k16.row.col.f32.f16.f16.f32 " \
                 "{%0,%1,%2,%3},{%4,%5,%6,%7},{%8,%9},{%0,%1,%2,%3};" \
                 : "+f"(d[0]), "+f"(d[1]), "+f"(d[2]), "+f"(d[3]) \
                 : "r"(a[0]), "r"(a[1]), "r"(a[2]), "r"(a[3]), "r"(b[0]), "r"(b[1]))

// ---------------- prep: P/Q basis (fp16, MUFU) + all weight converts + padded bias ----------------
#define NB_BAS (NPQ2*KPQ)
#define NV_W   (CH*CH/4)
#define NV_WO  (TC*CH/4)
#define PREP_TOTAL (NB_BAS + 3*NV_W + NV_WO + TC)
__global__ void prep_k(const float* __restrict__ w0, const float* __restrict__ w1,
                       const float* __restrict__ w2, const float* __restrict__ wo,
                       const float* __restrict__ b_out) {
    int idx = blockIdx.x*blockDim.x + threadIdx.x;
    if (idx < NB_BAS) {
        int row = idx / KPQ;
        int k = idx - row*KPQ;
        bool is_sin = (row >= NPQ);
        int t = is_sin ? row - NPQ : row;
        float val = 0.f;
        if (k < NC) {
            int m = (k * t) & (WIN - 1);
            int mm = (m < 256) ? m : m - 512;            // theta in [-pi, pi)
            float theta = (float)mm * (float)(M_PI/256.0);
            float w = (k == 0 || k == NC-1) ? 1.f : 2.f;
            float v = is_sin ? __sinf(theta) : __cosf(theta);
            val = v * w * (1.f/512.f);
        }
        g_basPQ[idx] = __float2half(val);
        return;
    }
    int r = idx - NB_BAS;
    const float* src; bf* hi; bf* lo;
    if      (r < NV_W)          { src = w0; hi = g_w0h; lo = g_w0l; }
    else if (r < 2*NV_W)        { src = w1; hi = g_w1h; lo = g_w1l; r -= NV_W; }
    else if (r < 3*NV_W)        { src = w2; hi = g_w2h; lo = g_w2l; r -= 2*NV_W; }
    else if (r < 3*NV_W+NV_WO)  { src = wo; hi = g_woh; lo = g_wol; r -= 3*NV_W; }
    else if (r < 3*NV_W+NV_WO+TC) { g_bout[r - 3*NV_W - NV_WO] = b_out[r - 3*NV_W - NV_WO]; return; }
    else return;
    int i = r*4;
    float4 v = *(const float4*)(src + i);
    bf h0,h1,h2,h3,l0,l1,l2,l3;
    split1(v.x,h0,l0); split1(v.y,h1,l1); split1(v.z,h2,l2); split1(v.w,h3,l3);
    __nv_bfloat162 hh0 = {h0,h1}, hh1 = {h2,h3}, ll0 = {l0,l1}, ll1 = {l2,l3};
    *(uint2*)(hi + i) = make_uint2(*(unsigned*)&hh0, *(unsigned*)&hh1);
    *(uint2*)(lo + i) = make_uint2(*(unsigned*)&ll0, *(unsigned*)&ll1);
}

// ---------------- fused proj + addpos + split ----------------
__global__ void proj_addpos_k(const float* __restrict__ param, const float* __restrict__ proj_w,
                              const float* __restrict__ proj_b, const float* __restrict__ pos) {
    int b = blockIdx.x;
    int c = threadIdx.x;                    // 256
    __shared__ float pr[CTX];
    __shared__ float bs[CH];
    if (c < CTX) pr[c] = param[b*CTX + c];
    __syncthreads();
    float acc = proj_b[c];
    const float* wr = proj_w + (size_t)c*CTX;
    #pragma unroll 8
    for (int k = 0; k < CTX; ++k) acc = fmaf(pr[k], wr[k], acc);
    bs[c] = acc;
    __syncthreads();
    int c4 = (c & 63) * 4;
    int f0 = c >> 6;
    float4 vb = *(const float4*)&bs[c4];
    #pragma unroll 4
    for (int i = 0; i < 32; ++i) {
        int f = f0 + i*4;
        float4 vp = *(const float4*)(pos + (size_t)f*CH + c4);
        float4 v = make_float4(vb.x+vp.x, vb.y+vp.y, vb.z+vp.z, vb.w+vp.w);
        bf h0,h1,h2,h3,l0,l1,l2,l3;
        split1(v.x,h0,l0); split1(v.y,h1,l1); split1(v.z,h2,l2); split1(v.w,h3,l3);
        __nv_bfloat162 hh0 = {h0,h1}, hh1 = {h2,h3}, ll0 = {l0,l1}, ll1 = {l2,l3};
        size_t o = (size_t)(b*NF + f)*CH + c4;
        *(uint2*)(g_a0h + o) = make_uint2(*(unsigned*)&hh0, *(unsigned*)&hh1);
        *(uint2*)(g_a0l + o) = make_uint2(*(unsigned*)&ll0, *(unsigned*)&ll1);
    }
}

// ---------------- bf16 3-term GEMM (BM=64, BN=64, BK=32, 256 thr, 3-stage, split acc)
#define SM_TILE (64*40)
#define SM_STAGE (2*SM_TILE)
#define SM_HALF (3*SM_STAGE)
#define SMEM_BYTES (2*SM_HALF*2)

template<bool RELU, bool BIAS, bool SPLITOUT>
__global__ void __launch_bounds__(256) gemm7_k(
    const bf* __restrict__ Ah, const bf* __restrict__ Al,
    const bf* __restrict__ Wh, const bf* __restrict__ Wl,
    const float* __restrict__ bias,
    float* __restrict__ Cf, bf* __restrict__ Ch, bf* __restrict__ Cl,
    int M, int N, int K, int lda, int ldw, int ldc)
{
    extern __shared__ __align__(16) bf sm[];
    bf* sA = sm;
    bf* sB = sm + SM_HALF;

    int tid = threadIdx.x;
    int row0 = blockIdx.y * 64;
    int col0 = blockIdx.x * 64;

    int lrow = tid >> 2;
    int lch  = (tid & 3) * 8;

    int wid  = tid >> 5;
    int lane = tid & 31;
    int wm0 = (wid >> 1) * 16;
    int wn0 = (wid & 1) * 32;
    int t = lane & 3;

    int q  = lane >> 3;
    int r8 = lane & 7;
    int a_row = wm0 + ((q & 1) << 3) + r8;
    int a_col = (q >> 1) << 3;
    int b_row = ((q >> 1) << 3) + r8;
    int b_col = (q & 1) << 3;

    auto prefetch = [&](int kt, int st) {
        int gk = kt*32 + lch;
        bf* pa = sA + st*SM_STAGE + lrow*40 + lch;
        bf* pb = sB + st*SM_STAGE + lrow*40 + lch;
        cp16(pa,           Ah + (size_t)(row0+lrow)*lda + gk);
        cp16(pa + SM_TILE, Al + (size_t)(row0+lrow)*lda + gk);
        cp16(pb,           Wh + (size_t)(col0+lrow)*ldw + gk);
        cp16(pb + SM_TILE, Wl + (size_t)(col0+lrow)*ldw + gk);
    };

    float acch[4][4], accl[4][4];
    #pragma unroll
    for (int nt = 0; nt < 4; ++nt)
        #pragma unroll
        for (int i = 0; i < 4; ++i) { acch[nt][i] = 0.f; accl[nt][i] = 0.f; }

    int ktiles = K >> 5;
    prefetch(0, 0); CP_COMMIT();
    prefetch(1, 1); CP_COMMIT();

    for (int kt = 0; kt < ktiles; ++kt) {
        int st = kt % 3;
        if (kt + 1 < ktiles) { CP_WAIT1(); } else { CP_WAIT0(); }
        __syncthreads();
        const bf* cA = sA + st*SM_STAGE;
        const bf* cB = sB + st*SM_STAGE;

        #pragma unroll
        for (int kk = 0; kk < 32; kk += 16) {
            unsigned ah[4], al[4], bh[4][2], bl[4][2];
            ldsm4(ah[0], ah[1], ah[2], ah[3], cA + a_row*40 + kk + a_col);
            ldsm4(al[0], al[1], al[2], al[3], cA + SM_TILE + a_row*40 + kk + a_col);
            ldsm4(bh[0][0], bh[0][1], bh[1][0], bh[1][1], cB + (wn0      + b_row)*40 + kk + b_col);
            ldsm4(bh[2][0], bh[2][1], bh[3][0], bh[3][1], cB + (wn0 + 16 + b_row)*40 + kk + b_col);
            ldsm4(bl[0][0], bl[0][1], bl[1][0], bl[1][1], cB + SM_TILE + (wn0      + b_row)*40 + kk + b_col);
            ldsm4(bl[2][0], bl[2][1], bl[3][0], bl[3][1], cB + SM_TILE + (wn0 + 16 + b_row)*40 + kk + b_col);
            #pragma unroll
            for (int nt = 0; nt < 4; ++nt) {
                MMA_BF16(acch[nt], ah, bh[nt]);
                MMA_BF16(accl[nt], ah, bl[nt]);
                MMA_BF16(accl[nt], al, bh[nt]);
            }
        }
        if (kt + 2 < ktiles) { prefetch(kt + 2, (kt + 2) % 3); CP_COMMIT(); }
    }

    int g = lane >> 2;
    #pragma unroll
    for (int nt = 0; nt < 4; ++nt) {
        int c = col0 + wn0 + nt*8 + 2*t;
        float b0 = BIAS ? bias[c]   : 0.f;
        float b1 = BIAS ? bias[c+1] : 0.f;
        int r0 = row0 + wm0 + g;
        float v[4] = {acch[nt][0] + accl[nt][0] + b0, acch[nt][1] + accl[nt][1] + b1,
                      acch[nt][2] + accl[nt][2] + b0, acch[nt][3] + accl[nt][3] + b1};
        if (RELU) {
            #pragma unroll
            for (int qq = 0; qq < 4; ++qq) v[qq] = (v[qq] > 0.f) ? v[qq] : 0.2f*v[qq];
        }
        if (SPLITOUT) {
            bf h0,h1,h2,h3,l0,l1,l2,l3;
            split1(v[0],h0,l0); split1(v[1],h1,l1);
            split1(v[2],h2,l2); split1(v[3],h3,l3);
            __nv_bfloat162 hA = {h0,h1}, hB = {h2,h3}, lA = {l0,l1}, lB = {l2,l3};
            *(__nv_bfloat162*)(Ch + (size_t)r0*ldc + c)     = hA;
            *(__nv_bfloat162*)(Ch + (size_t)(r0+8)*ldc + c) = hB;
            *(__nv_bfloat162*)(Cl + (size_t)r0*ldc + c)     = lA;
            *(__nv_bfloat162*)(Cl + (size_t)(r0+8)*ldc + c) = lB;
        } else {
            *(float2*)(Cf + (size_t)r0*ldc + c)     = make_float2(v[0], v[1]);
            *(float2*)(Cf + (size_t)(r0+8)*ldc + c) = make_float2(v[2], v[3]);
        }
    }
}

// ---------------- fp16 1-term GEMM (P/Q irfft path): spec single fp16 x basis fp16 ----------------
#define HSM_TILE (64*40)
#define HA_TOTAL (3*HSM_TILE)
#define SMEMH_BYTES ((3*HSM_TILE + 3*HSM_TILE)*2)   // 30720

__global__ void __launch_bounds__(256) gemmh_k(
    const hf* __restrict__ A0,
    const hf* __restrict__ W,
    float* __restrict__ Cf,
    int K, int lda, int ldw, int ldc)
{
    extern __shared__ __align__(16) hf smh[];
    hf* sA = smh;
    hf* sB = smh + HA_TOTAL;

    int tid = threadIdx.x;
    int row0 = blockIdx.y * 64;
    int col0 = blockIdx.x * 64;
    const hf* Ah = (col0 >= NPQ) ? A0 + IMOFF : A0;

    int lrow = tid >> 2;
    int lch  = (tid & 3) * 8;

    int wid  = tid >> 5;
    int lane = tid & 31;
    int wm0 = (wid >> 1) * 16;
    int wn0 = (wid & 1) * 32;
    int t = lane & 3;

    int q  = lane >> 3;
    int r8 = lane & 7;
    int a_row = wm0 + ((q & 1) << 3) + r8;
    int a_col = (q >> 1) << 3;
    int b_row = ((q >> 1) << 3) + r8;
    int b_col = (q & 1) << 3;

    auto prefetch = [&](int kt, int st) {
        int gk = kt*32 + lch;
        cp16(sA + st*HSM_TILE + lrow*40 + lch, Ah + (size_t)(row0+lrow)*lda + gk);
        cp16(sB + st*HSM_TILE + lrow*40 + lch, W  + (size_t)(col0+lrow)*ldw + gk);
    };

    float acc[4][4];
    #pragma unroll
    for (int nt = 0; nt < 4; ++nt)
        #pragma unroll
        for (int i = 0; i < 4; ++i) acc[nt][i] = 0.f;

    int ktiles = K >> 5;
    prefetch(0, 0); CP_COMMIT();
    prefetch(1, 1); CP_COMMIT();

    for (int kt = 0; kt < ktiles; ++kt) {
        int st = kt % 3;
        if (kt + 1 < ktiles) { CP_WAIT1(); } else { CP_WAIT0(); }
        __syncthreads();
        const hf* cA = sA + st*HSM_TILE;
        const hf* cB = sB + st*HSM_TILE;

        #pragma unroll
        for (int kk = 0; kk < 32; kk += 16) {
            unsigned ah[4], bh[4][2];
            ldsm4(ah[0], ah[1], ah[2], ah[3], cA + a_row*40 + kk + a_col);
            ldsm4(bh[0][0], bh[0][1], bh[1][0], bh[1][1], cB + (wn0      + b_row)*40 + kk + b_col);
            ldsm4(bh[2][0], bh[2][1], bh[3][0], bh[3][1], cB + (wn0 + 16 + b_row)*40 + kk + b_col);
            #pragma unroll
            for (int nt = 0; nt < 4; ++nt)
                MMA_F16(acc[nt], ah, bh[nt]);
        }
        if (kt + 2 < ktiles) { prefetch(kt + 2, (kt + 2) % 3); CP_COMMIT(); }
    }

    int g = lane >> 2;
    #pragma unroll
    for (int nt = 0; nt < 4; ++nt) {
        int c = col0 + wn0 + nt*8 + 2*t;
        int r0 = row0 + wm0 + g;
        *(float2*)(Cf + (size_t)r0*ldc + c)     = make_float2(acc[nt][0], acc[nt][1]);
        *(float2*)(Cf + (size_t)(r0+8)*ldc + c) = make_float2(acc[nt][2], acc[nt][3]);
    }
}

// ---------------- fused phase cumsum + complex exp -> spec single fp16 ----------------
// grid (BB, 4); block (66, 8): k = by*66 + tx; chunk = ty (16 frames each).
__global__ void spec_k(const float* __restrict__ noise) {
    int b = blockIdx.x;
    int kk = threadIdx.x;                       // 0..65
    int k = blockIdx.y*66 + kk;
    int chunk = threadIdx.y;                    // 0..7
    __shared__ float cs[8][66];
    bool act = (k < NC);
    float freqpi = (float)k * (float)(M_PI/256.0);
    const float* xp = g_xout + (size_t)b*NF*TCL + (size_t)chunk*16*TCL;
    const float* np = noise  + (size_t)b*NF*NC + (size_t)chunk*16*NC + k;
    float s = 0.f;
    if (act) {
        const float* xq = xp + 2*k + 1;
        #pragma unroll 4
        for (int f = 0; f < 16; ++f)
            s = fmaf(fmaf(xq[(size_t)f*TCL], np[(size_t)f*NC], 1.f), freqpi, s);
    }
    cs[chunk][kk] = s;
    __syncthreads();
    if (!act) return;
    float p = 0.f;
    for (int c = 0; c < chunk; ++c) p += cs[c][kk];
    const float* xq = xp + 2*k;
    size_t o0 = (size_t)b*NF*TCL + (size_t)chunk*16*TCL + k;
    const float TWO_PI = 6.28318530717958647692f;
    const float INV_2PI = 0.15915494309189533577f;
    for (int f = 0; f < 16; ++f) {
        float mg = fabsf(xq[(size_t)f*TCL]);
        float ph = xq[(size_t)f*TCL + 1];
        float ns = np[(size_t)f*NC];
        p = fmaf(fmaf(ph, ns, 1.f), freqpi, p);
        float r = p - TWO_PI * rintf(p * INV_2PI);
        float sn, c;
        __sincosf(r, &sn, &c);
        size_t o = o0 + (size_t)f*TCL;
        g_sphH[o]         = __float2half(mg * c);
        g_sphH[o + IMOFF] = __float2half(mg * sn);
    }
}

// ---------------- overlap-add (from P/Q, hann applied here) + extract (fused) ----------------
__global__ void sig_ext_k(const float* __restrict__ times) {
    if (blockIdx.x < 4096) {
        int idx = blockIdx.x*256 + threadIdx.x;
        int b = idx >> 15;
        int s = idx & (NS-1);
        int f0 = s >> 8;
        int r = s & 255;
        const float PI256 = (float)(M_PI/256.0);
        const float* pq = g_pq + (size_t)(b*NF + f0)*NPQ2;
        float hann1 = 0.5f*(1.f - __cosf((float)r * PI256));
        float v = hann1 * (pq[r] - pq[NPQ + r]);
        if (f0 > 0) {
            const float* pq2 = g_pq + (size_t)(b*NF + f0 - 1)*NPQ2;
            int t = r + 256;
            float hann2 = 0.5f*(1.f - __cosf((float)t * PI256));
            float raw2;
            if (r == 0) raw2 = pq2[256] - pq2[NPQ + 256];
            else { int u = 256 - r; raw2 = pq2[u] + pq2[NPQ + u]; }
            v += hann2 * raw2;
        }
        g_sig[idx] = v;
    } else {
        int be = (blockIdx.x - 4096)*256 + threadIdx.x;
        if (be >= BB*NE) return;
        int cnt = 0;
        for (int f = 0; f < NF; ++f) {
            float v = times[(size_t)be*NF + f];
            if (v != 0.f) { g_evf[be*NF + cnt] = f; g_eva[be*NF + cnt] = v; ++cnt; }
        }
        g_evcnt[be] = cnt;
    }
}

// ---------------- sparse shift-add convolution ----------------
__global__ void conv_k(float* __restrict__ out) {
    int be = blockIdx.y;
    int b = be >> 4;
    int t = (blockIdx.x*blockDim.x + threadIdx.x) * 4;
    int cnt = g_evcnt[be];
    const float* sg = g_sig + (size_t)b*NS;
    float4 acc = make_float4(0.f, 0.f, 0.f, 0.f);
    for (int j = 0; j < cnt; ++j) {
        int f = g_evf[be*NF + j];
        float a = g_eva[be*NF + j];
        int s = t - (f << 8);
        if (s >= 0) {
            float4 v = *(const float4*)(sg + s);
            acc.x = fmaf(a, v.x, acc.x);
            acc.y = fmaf(a, v.y, acc.y);
            acc.z = fmaf(a, v.z, acc.z);
            acc.w = fmaf(a, v.w, acc.w);
        }
    }
    *(float4*)(out + (size_t)be*NS + t) = acc;
}

// ---------------- launch ----------------
extern "C" void kernel_launch(void* const* d_in, const int* in_sizes, int n_in,
                              void* d_out, int out_size) {
    const float* param  = (const float*)d_in[0];
    const float* times  = (const float*)d_in[1];
    const float* noise  = (const float*)d_in[2];
    const float* pos    = (const float*)d_in[3];
    const float* proj_w = (const float*)d_in[4];
    const float* proj_b = (const float*)d_in[5];
    const float* w0     = (const float*)d_in[6];
    const float* b0     = (const float*)d_in[7];
    const float* w1     = (const float*)d_in[8];
    const float* b1     = (const float*)d_in[9];
    const float* w2     = (const float*)d_in[10];
    const float* b2     = (const float*)d_in[11];
    const float* w_out  = (const float*)d_in[12];
    const float* b_out  = (const float*)d_in[13];
    float* out = (float*)d_out;

    float *xout, *pq, *bout;
    bf *a0h,*a0l,*a1h,*a1l,*w0h,*w0l,*w1h,*w1l,*w2h,*w2l,*woh,*wol;
    hf *basPQ,*sphH;
    cudaGetSymbolAddress((void**)&xout, g_xout);
    cudaGetSymbolAddress((void**)&pq,   g_pq);
    cudaGetSymbolAddress((void**)&bout, g_bout);
    cudaGetSymbolAddress((void**)&a0h, g_a0h); cudaGetSymbolAddress((void**)&a0l, g_a0l);
    cudaGetSymbolAddress((void**)&a1h, g_a1h); cudaGetSymbolAddress((void**)&a1l, g_a1l);
    cudaGetSymbolAddress((void**)&w0h, g_w0h); cudaGetSymbolAddress((void**)&w0l, g_w0l);
    cudaGetSymbolAddress((void**)&w1h, g_w1h); cudaGetSymbolAddress((void**)&w1l, g_w1l);
    cudaGetSymbolAddress((void**)&w2h, g_w2h); cudaGetSymbolAddress((void**)&w2l, g_w2l);
    cudaGetSymbolAddress((void**)&woh, g_woh); cudaGetSymbolAddress((void**)&wol, g_wol);
    cudaGetSymbolAddress((void**)&basPQ, g_basPQ);
    cudaGetSymbolAddress((void**)&sphH, g_sphH);

    static bool attr_done = false;
    if (!attr_done) {
        cudaFuncSetAttribute(gemm7_k<true,  true,  true >, cudaFuncAttributeMaxDynamicSharedMemorySize, SMEM_BYTES);
        cudaFuncSetAttribute(gemm7_k<false, true,  false>, cudaFuncAttributeMaxDynamicSharedMemorySize, SMEM_BYTES);
        cudaFuncSetAttribute(gemmh_k, cudaFuncAttributeMaxDynamicSharedMemorySize, SMEMH_BYTES);
        attr_done = true;
    }

    prep_k<<<(PREP_TOTAL + 255)/256, 256>>>(w0, w1, w2, w_out, b_out);
    proj_addpos_k<<<BB, 256>>>(param, proj_w, proj_b, pos);

    // MLP layers (bf16 3-term)
    gemm7_k<true, true, true><<<dim3(4, 64), 256, SMEM_BYTES>>>(
        a0h, a0l, w0h, w0l, b0, (float*)0, a1h, a1l, NROWS, CH, CH, CH, CH, CH);
    gemm7_k<true, true, true><<<dim3(4, 64), 256, SMEM_BYTES>>>(
        a1h, a1l, w1h, w1l, b1, (float*)0, a0h, a0l, NROWS, CH, CH, CH, CH, CH);
    gemm7_k<true, true, true><<<dim3(4, 64), 256, SMEM_BYTES>>>(
        a0h, a0l, w2h, w2l, b2, (float*)0, a1h, a1l, NROWS, CH, CH, CH, CH, CH);
    // out layer (bf16 3-term): padded N=576, fp32 out, ldc=TCL
    gemm7_k<false, true, false><<<dim3(9, 64), 256, SMEM_BYTES>>>(
        a1h, a1l, woh, wol, bout, xout, (bf*)0, (bf*)0, NROWS, NWO, CH, CH, CH, TCL);

    spec_k<<<dim3(BB, 4), dim3(66, 8)>>>(noise);

    // P|Q = spec_{re|im} @ {cos|sin}Basis^T (fp16 1-term; K=288, N=640)
    gemmh_k<<<dim3(10, 64), 256, SMEMH_BYTES>>>(
        sphH, basPQ, pq, KPQ, TCL, KPQ, NPQ2);

    sig_ext_k<<<4098, 256>>>(times);
    conv_k<<<dim3(NS/1024, BB*NE), 256>>>(out);
}